// round 11
// baseline (speedup 1.0000x reference)
#include <cuda_runtime.h>
#include <cstdint>

// tokens: int32[4194304] (values in [0,128)), ls: float32[128,2,2], final (unused)
// output: float32[2] = row 0 of ordered product of ls[tokens[t]], last token applied twice.

#define TPB 256
#define NBLK 296                 // 2 blocks per SM (148 SMs), even placement
#define NTILES 1024              // 4194304 / 4096
#define TILE_TOK 4096
#define TILE_I4 1024             // int4 chunks per tile

__device__ float4 g_part[NTILES];
__device__ unsigned g_count = 0;

// C = A @ B, row-major 2x2 packed in float4 (x=m00, y=m01, z=m10, w=m11)
__device__ __forceinline__ float4 mm2(float4 A, float4 B) {
    float4 C;
    C.x = fmaf(A.x, B.x, A.y * B.z);
    C.y = fmaf(A.x, B.y, A.y * B.w);
    C.z = fmaf(A.z, B.x, A.w * B.z);
    C.w = fmaf(A.z, B.y, A.w * B.w);
    return C;
}

// Order-preserving pairwise warp reduction; lane 0 ends with ordered product.
__device__ __forceinline__ float4 warp_reduce_ordered(float4 M, unsigned lane) {
    #pragma unroll
    for (int off = 1; off < 32; off <<= 1) {
        float4 B;
        B.x = __shfl_down_sync(0xffffffffu, M.x, off);
        B.y = __shfl_down_sync(0xffffffffu, M.y, off);
        B.z = __shfl_down_sync(0xffffffffu, M.z, off);
        B.w = __shfl_down_sync(0xffffffffu, M.w, off);
        if ((lane & (2 * off - 1)) == 0) M = mm2(M, B);
    }
    return M;
}

// 16B-granule swizzle inside one tile buffer (index in [0,1024)).
__device__ __forceinline__ unsigned swz10(unsigned i) { return i ^ ((i >> 3) & 7u); }

__device__ __forceinline__ void cp16(void* smem_dst, const int4* gsrc) {
    uint32_t s = (uint32_t)__cvta_generic_to_shared(smem_dst);
    asm volatile("cp.async.cg.shared.global [%0], [%1], 16;"
                 :: "r"(s), "l"(gsrc) : "memory");
}
__device__ __forceinline__ void cp_commit() {
    asm volatile("cp.async.commit_group;" ::: "memory");
}
template <int N> __device__ __forceinline__ void cp_wait() {
    asm volatile("cp.async.wait_group %0;" :: "n"(N) : "memory");
}

__global__ void __launch_bounds__(TPB)
chain_pipe_kernel(const int* __restrict__ tokens,
                  const float* __restrict__ ls,
                  float* __restrict__ out,
                  int n_tokens) {
    // Replicated table: entry j, replica r at byte j*128 + r*16.
    // Lane l reads replica (l&7) -> fixed bank group, uniform 4-way = floor.
    __shared__ __align__(16) char s_tab[128 * 128];    // 16 KB
    __shared__ int4   s_buf[2][TILE_I4];               // 32 KB double-buffered tokens
    __shared__ float4 s_warp[TPB / 32];
    __shared__ bool   s_is_last;

    const unsigned tid  = threadIdx.x;
    const unsigned lane = tid & 31u;
    const unsigned wid  = tid >> 5;

    const int4* __restrict__ tok4 = reinterpret_cast<const int4*>(tokens);

    // ── Build replicated table once per block (rotated, conflict-free writes).
    if (tid < 128) {
        float4 e = reinterpret_cast<const float4*>(ls)[tid];
        #pragma unroll
        for (int r = 0; r < 8; r++) {
            unsigned r_eff = (r + tid) & 7u;
            *reinterpret_cast<float4*>(s_tab + tid * 128 + r_eff * 16) = e;
        }
    }

    // ── Prologue: async-copy first tile into buffer 0 (swizzled destinations).
    {
        const int4* src = tok4 + (size_t)blockIdx.x * TILE_I4;
        #pragma unroll
        for (int k = 0; k < 4; k++)
            cp16(&s_buf[0][swz10(tid + 256 * k)], src + tid + 256 * k);
        cp_commit();
    }

    int buf = 0;
    const unsigned rbase = (lane & 7u) * 16u;   // this lane's replica column

    for (int tile = blockIdx.x; tile < NTILES; tile += NBLK) {
        const int nxt = tile + NBLK;
        if (nxt < NTILES) {
            // Prefetch next tile into the other buffer, then wait for current.
            const int4* src = tok4 + (size_t)nxt * TILE_I4;
            #pragma unroll
            for (int k = 0; k < 4; k++)
                cp16(&s_buf[buf ^ 1][swz10(tid + 256 * k)], src + tid + 256 * k);
            cp_commit();
            cp_wait<1>();
        } else {
            cp_wait<0>();
        }
        __syncthreads();   // current buffer visible to all threads

        // ── Compute: 16 contiguous tokens per thread, 4 independent chains.
        int4 t0 = s_buf[buf][swz10(4 * tid + 0)];
        int4 t1 = s_buf[buf][swz10(4 * tid + 1)];
        int4 t2 = s_buf[buf][swz10(4 * tid + 2)];
        int4 t3 = s_buf[buf][swz10(4 * tid + 3)];

        #define TAB(tok) (*reinterpret_cast<const float4*>( \
            s_tab + (((unsigned)(tok) & 127u) << 7) + rbase))

        float4 A = TAB(t0.x);
        float4 B = TAB(t1.x);
        float4 C = TAB(t2.x);
        float4 D = TAB(t3.x);
        A = mm2(A, TAB(t0.y));  B = mm2(B, TAB(t1.y));
        C = mm2(C, TAB(t2.y));  D = mm2(D, TAB(t3.y));
        A = mm2(A, TAB(t0.z));  B = mm2(B, TAB(t1.z));
        C = mm2(C, TAB(t2.z));  D = mm2(D, TAB(t3.z));
        A = mm2(A, TAB(t0.w));  B = mm2(B, TAB(t1.w));
        C = mm2(C, TAB(t2.w));  D = mm2(D, TAB(t3.w));
        float4 M = mm2(mm2(A, B), mm2(C, D));
        #undef TAB

        // ── Ordered block reduction -> per-tile partial.
        M = warp_reduce_ordered(M, lane);
        if (lane == 0) s_warp[wid] = M;
        __syncthreads();

        if (tid == 0) {
            float4 R = s_warp[0];
            #pragma unroll
            for (int wI = 1; wI < TPB / 32; wI++) R = mm2(R, s_warp[wI]);
            g_part[tile] = R;              // ordered by tile index
        }
        buf ^= 1;
    }

    // ── Completion: one atomic per block (R6-verified protocol).
    __syncthreads();
    if (tid == 0) {
        __threadfence();                   // publish this block's partials
        unsigned old = atomicAdd(&g_count, 1u);
        s_is_last = (old == NBLK - 1);
    }
    __syncthreads();

    // ── Tail: last block combines all 1024 tile partials in order.
    if (s_is_last) {
        __threadfence();
        const int base = tid * 4;          // 1024 / 256

        float4 P0 = g_part[base + 0];
        float4 P1 = g_part[base + 1];
        float4 P2 = g_part[base + 2];
        float4 P3 = g_part[base + 3];
        float4 P  = mm2(mm2(P0, P1), mm2(P2, P3));

        P = warp_reduce_ordered(P, lane);
        if (lane == 0) s_warp[wid] = P;
        __syncthreads();

        if (tid == 0) {
            float4 R = s_warp[0];
            #pragma unroll
            for (int wI = 1; wI < TPB / 32; wI++) R = mm2(R, s_warp[wI]);

            // Faithful to reference: last token's matrix applied a second time.
            int last = tokens[n_tokens - 1];
            float4 L = *reinterpret_cast<const float4*>(s_tab + ((unsigned)last << 7));
            R = mm2(R, L);

            out[0] = R.x;   // v = [1,0] @ R -> row 0
            out[1] = R.y;

            atomicExch(&g_count, 0u);   // reset for next graph replay
        }
    }
}

extern "C" void kernel_launch(void* const* d_in, const int* in_sizes, int n_in,
                              void* d_out, int out_size) {
    const int*   tokens = (const int*)d_in[0];
    const float* ls     = (const float*)d_in[1];
    float* out = (float*)d_out;

    const int n = in_sizes[0];             // 4194304
    chain_pipe_kernel<<<NBLK, TPB>>>(tokens, ls, out, n);
}

// round 12
// speedup vs baseline: 1.0103x; 1.0103x over previous
#include <cuda_runtime.h>

// tokens: int32[4194304] (values in [0,128)), ls: float32[128,2,2], final (unused)
// output: float32[2] = row 0 of ordered product of ls[tokens[t]], last token applied twice.

#define TPB 256
#define TOK_PER_THREAD 16
#define TOK_PER_BLOCK (TPB * TOK_PER_THREAD)   // 4096
#define MAX_BLOCKS 4096

__device__ float4 g_part[MAX_BLOCKS];
__device__ unsigned g_count = 0;

// C = A @ B, row-major 2x2 packed in float4 (x=m00, y=m01, z=m10, w=m11)
__device__ __forceinline__ float4 mm2(float4 A, float4 B) {
    float4 C;
    C.x = fmaf(A.x, B.x, A.y * B.z);
    C.y = fmaf(A.x, B.y, A.y * B.w);
    C.z = fmaf(A.z, B.x, A.w * B.z);
    C.w = fmaf(A.z, B.y, A.w * B.w);
    return C;
}

// Order-preserving pairwise warp reduction; lane 0 ends with ordered product.
__device__ __forceinline__ float4 warp_reduce_ordered(float4 M, unsigned lane) {
    #pragma unroll
    for (int off = 1; off < 32; off <<= 1) {
        float4 B;
        B.x = __shfl_down_sync(0xffffffffu, M.x, off);
        B.y = __shfl_down_sync(0xffffffffu, M.y, off);
        B.z = __shfl_down_sync(0xffffffffu, M.z, off);
        B.w = __shfl_down_sync(0xffffffffu, M.w, off);
        if ((lane & (2 * off - 1)) == 0) M = mm2(M, B);
    }
    return M;
}

__global__ void __launch_bounds__(TPB)
chain_warp_kernel(const int* __restrict__ tokens,
                  const float* __restrict__ ls,
                  float* __restrict__ out,
                  int n_tokens) {
    // Replicated table: entry j, replica r at byte j*128 + r*16.
    // Lane l reads replica (l&7) -> fixed bank group, uniform 4-way = floor.
    __shared__ __align__(16) char      s_tab[128 * 128];   // 16 KB
    __shared__ __align__(16) unsigned  s_pack[8 * 128];    // 4 KB: 512B slice per warp
    __shared__ float4                  s_warp[TPB / 32];
    __shared__ bool                    s_is_last;

    const unsigned tid  = threadIdx.x;
    const unsigned lane = tid & 31u;
    const unsigned wid  = tid >> 5;
    const unsigned nblk = gridDim.x;

    // ── Each warp's 512 contiguous tokens; 4 coalesced LDG.128 per lane
    //    (round-major: round r covers chunk r*32+lane). Issue before the
    //    table barrier so DRAM latency hides under it.
    const int4* __restrict__ tok4 = reinterpret_cast<const int4*>(tokens);
    const unsigned warp_i4 = (blockIdx.x * 8u + wid) * 128u;
    int4 a0 = tok4[warp_i4 + lane];
    int4 a1 = tok4[warp_i4 + lane + 32];
    int4 a2 = tok4[warp_i4 + lane + 64];
    int4 a3 = tok4[warp_i4 + lane + 96];

    // ── Replicated table build (rotated, conflict-free writes).
    if (tid < 128) {
        float4 e = reinterpret_cast<const float4*>(ls)[tid];
        #pragma unroll
        for (int r = 0; r < 8; r++) {
            unsigned r_eff = (r + tid) & 7u;
            *reinterpret_cast<float4*>(s_tab + tid * 128 + r_eff * 16) = e;
        }
    }
    __syncthreads();   // table visible; the ONLY pre-compute block barrier

    // ── Warp-private staging: pack 4 tokens/word, round-major STS (coalesced,
    //    conflict-free), then lane-contiguous LDS.128. Only __syncwarp needed.
    unsigned* wslice = s_pack + wid * 128;
    wslice[lane]      = (unsigned)a0.x | ((unsigned)a0.y << 8) | ((unsigned)a0.z << 16) | ((unsigned)a0.w << 24);
    wslice[lane + 32] = (unsigned)a1.x | ((unsigned)a1.y << 8) | ((unsigned)a1.z << 16) | ((unsigned)a1.w << 24);
    wslice[lane + 64] = (unsigned)a2.x | ((unsigned)a2.y << 8) | ((unsigned)a2.z << 16) | ((unsigned)a2.w << 24);
    wslice[lane + 96] = (unsigned)a3.x | ((unsigned)a3.y << 8) | ((unsigned)a3.z << 16) | ((unsigned)a3.w << 24);
    __syncwarp();

    // Lane's 16 contiguous tokens = one LDS.128 (contiguous 512B per warp).
    const uint4 w = reinterpret_cast<const uint4*>(wslice)[lane];
    __syncwarp();                        // safe to not overwrite before all read
    const unsigned rbase = (lane & 7u) * 16u;

    #define TAB(word, sh) (*reinterpret_cast<const float4*>( \
        s_tab + ((((word) >> (sh)) & 127u) << 7) + rbase))

    // ── Phase 1: four independent 4-token chains, tree-combined (ordered).
    float4 A = TAB(w.x, 0);
    float4 B = TAB(w.y, 0);
    float4 C = TAB(w.z, 0);
    float4 D = TAB(w.w, 0);
    A = mm2(A, TAB(w.x,  8));  B = mm2(B, TAB(w.y,  8));
    C = mm2(C, TAB(w.z,  8));  D = mm2(D, TAB(w.w,  8));
    A = mm2(A, TAB(w.x, 16));  B = mm2(B, TAB(w.y, 16));
    C = mm2(C, TAB(w.z, 16));  D = mm2(D, TAB(w.w, 16));
    A = mm2(A, TAB(w.x, 24));  B = mm2(B, TAB(w.y, 24));
    C = mm2(C, TAB(w.z, 24));  D = mm2(D, TAB(w.w, 24));
    float4 M = mm2(mm2(A, B), mm2(C, D));
    #undef TAB

    // ── Phase 2: per-warp ordered shuffle reduce; warps stay independent.
    M = warp_reduce_ordered(M, lane);
    if (lane == 0) s_warp[wid] = M;
    __syncthreads();   // end-of-block alignment (only other block barrier)

    if (tid == 0) {
        float4 R = s_warp[0];
        #pragma unroll
        for (int wI = 1; wI < TPB / 32; wI++) R = mm2(R, s_warp[wI]);
        g_part[blockIdx.x] = R;
        __threadfence();
        unsigned old = atomicAdd(&g_count, 1u);
        s_is_last = (old == nblk - 1);
    }
    __syncthreads();

    // ── Phase 3: last block combines all 1024 partials in order.
    if (s_is_last) {
        __threadfence();
        const int base = tid * 4;              // 1024/256

        float4 P0 = g_part[base + 0];
        float4 P1 = g_part[base + 1];
        float4 P2 = g_part[base + 2];
        float4 P3 = g_part[base + 3];
        float4 P  = mm2(mm2(P0, P1), mm2(P2, P3));

        P = warp_reduce_ordered(P, lane);
        if (lane == 0) s_warp[wid] = P;
        __syncthreads();

        if (tid == 0) {
            float4 R = s_warp[0];
            #pragma unroll
            for (int wI = 1; wI < TPB / 32; wI++) R = mm2(R, s_warp[wI]);

            // Faithful to reference: last token's matrix applied a second time.
            int last = tokens[n_tokens - 1];
            float4 L = *reinterpret_cast<const float4*>(s_tab + ((unsigned)last << 7));
            R = mm2(R, L);

            out[0] = R.x;   // v = [1,0] @ R -> row 0
            out[1] = R.y;

            atomicExch(&g_count, 0u);   // reset for next graph replay
        }
    }
}

extern "C" void kernel_launch(void* const* d_in, const int* in_sizes, int n_in,
                              void* d_out, int out_size) {
    const int*   tokens = (const int*)d_in[0];
    const float* ls     = (const float*)d_in[1];
    float* out = (float*)d_out;

    const int n = in_sizes[0];                 // 4194304
    const int nblocks = n / TOK_PER_BLOCK;     // 1024

    chain_warp_kernel<<<nblocks, TPB>>>(tokens, ls, out, n);
}